// round 6
// baseline (speedup 1.0000x reference)
#include <cuda_runtime.h>
#include <cuda_fp16.h>
#include <cstdint>

// Problem dims
#define BB 4
#define SS 4096
#define DD 256
#define CC 8921
#define CP 8960   // C padded to multiple of 128

// ---------------- device scratch (zero-initialized at module load) ----------
__device__ __align__(256) __half g_xh[BB * SS * DD];        // x in fp16, [b][s][d]
__device__ __align__(256) __half g_xT[BB * DD * SS];        // x^T fp16, [b][d][s]
__device__ __align__(256) __half g_Wh[CP * DD];             // W fp16, padded rows stay 0
__device__ __align__(256) __half g_e [BB * CP * SS];        // exp(scores), fp16
__device__ __align__(256) float  g_Z [BB * CP];             // row sums

// ---------------- helpers ---------------------------------------------------
__device__ __forceinline__ float fast_exp(float x) {
    // e^x via 2^(x*log2e), FFMA-only (no MUFU). |x| is small (<~10) here.
    float y = x * 1.4426950408889634f;
    y = fminf(fmaxf(y, -80.0f), 80.0f);
    float n = rintf(y);
    float f = y - n;
    float p = 1.3333558146e-3f;
    p = fmaf(p, f, 9.6181291076e-3f);
    p = fmaf(p, f, 5.5504108664e-2f);
    p = fmaf(p, f, 2.4022650696e-1f);
    p = fmaf(p, f, 6.9314718056e-1f);
    p = fmaf(p, f, 1.0f);
    return p * __int_as_float((__float2int_rn(n) + 127) << 23);
}

#define MMA16816(d, a, b)                                                     \
    asm volatile(                                                             \
        "mma.sync.aligned.m16n8k16.row.col.f32.f16.f16.f32 "                  \
        "{%0,%1,%2,%3}, {%4,%5,%6,%7}, {%8,%9}, {%0,%1,%2,%3};\n"             \
        : "+f"((d)[0]), "+f"((d)[1]), "+f"((d)[2]), "+f"((d)[3])              \
        : "r"((a)[0]), "r"((a)[1]), "r"((a)[2]), "r"((a)[3]),                 \
          "r"((b)[0]), "r"((b)[1]))

// ---------------- K0: convert inputs to fp16 (+ transpose of x) ------------
__global__ void k_convert(const float* __restrict__ x, const float* __restrict__ W) {
    int stride = gridDim.x * blockDim.x;
    int i0 = blockIdx.x * blockDim.x + threadIdx.x;
    for (int idx = i0; idx < BB * SS * DD; idx += stride) {
        float v = x[idx];
        __half h = __float2half(v);
        g_xh[idx] = h;
        int b = idx / (SS * DD);
        int r = idx - b * (SS * DD);
        int s = r >> 8;          // / DD
        int d = r & 255;         // % DD
        g_xT[(b * DD + d) * SS + s] = h;
    }
    for (int idx = i0; idx < CC * DD; idx += stride) {
        g_Wh[idx] = __float2half(W[idx]);
    }
}

// ---------------- K1: scores GEMM + exp -------------------------------------
// scores[c,s] = sum_d W[c,d]*x[s,d];  e = exp(score) -> g_e (fp16)
// CTA tile: 128(c) x 128(s), K=D=256 in chunks of 32. 8 warps = 2(m) x 4(n),
// warp tile 64x32, frags: 4(m) x 4(n) of m16n8k16.
#define KC 32
__global__ __launch_bounds__(256) void k_scores() {
    __shared__ __half As[128][KC + 8];
    __shared__ __half Bs[128][KC + 8];

    const int tid = threadIdx.x;
    const int wid = tid >> 5, lane = tid & 31;
    const int g = lane >> 2, tg = lane & 3;
    const int warp_m = wid >> 2, warp_n = wid & 3;

    const int c0 = blockIdx.x * 128;
    const int s0 = blockIdx.y * 128;
    const int b  = blockIdx.z;

    const __half* Wt = g_Wh + c0 * DD;
    const __half* Xt = g_xh + (b * SS + s0) * DD;

    float acc[4][4][4];
#pragma unroll
    for (int i = 0; i < 4; i++)
#pragma unroll
        for (int j = 0; j < 4; j++)
#pragma unroll
            for (int k = 0; k < 4; k++) acc[i][j][k] = 0.0f;

    // per-thread load slots: 512 int4 per tile (128 rows x 4 int4), 2 each
    const int slot0 = tid, slot1 = tid + 256;
    const int rA0 = slot0 >> 2, cA0 = (slot0 & 3) * 8;
    const int rA1 = slot1 >> 2, cA1 = (slot1 & 3) * 8;

    int4 pa0, pa1, pb0, pb1;
    pa0 = *(const int4*)(Wt + rA0 * DD + cA0);
    pa1 = *(const int4*)(Wt + rA1 * DD + cA1);
    pb0 = *(const int4*)(Xt + rA0 * DD + cA0);
    pb1 = *(const int4*)(Xt + rA1 * DD + cA1);

#pragma unroll 1
    for (int st = 0; st < DD / KC; st++) {
        __syncthreads();
        *(int4*)&As[rA0][cA0] = pa0;
        *(int4*)&As[rA1][cA1] = pa1;
        *(int4*)&Bs[rA0][cA0] = pb0;
        *(int4*)&Bs[rA1][cA1] = pb1;
        __syncthreads();
        if (st + 1 < DD / KC) {
            int kc = (st + 1) * KC;
            pa0 = *(const int4*)(Wt + rA0 * DD + kc + cA0);
            pa1 = *(const int4*)(Wt + rA1 * DD + kc + cA1);
            pb0 = *(const int4*)(Xt + rA0 * DD + kc + cA0);
            pb1 = *(const int4*)(Xt + rA1 * DD + kc + cA1);
        }
#pragma unroll
        for (int kk = 0; kk < KC; kk += 16) {
            uint32_t af[4][4], bf[4][2];
#pragma unroll
            for (int fm = 0; fm < 4; fm++) {
                int rb = warp_m * 64 + fm * 16;
                af[fm][0] = *(const uint32_t*)&As[rb + g    ][kk + 2 * tg    ];
                af[fm][1] = *(const uint32_t*)&As[rb + g + 8][kk + 2 * tg    ];
                af[fm][2] = *(const uint32_t*)&As[rb + g    ][kk + 2 * tg + 8];
                af[fm][3] = *(const uint32_t*)&As[rb + g + 8][kk + 2 * tg + 8];
            }
#pragma unroll
            for (int fn = 0; fn < 4; fn++) {
                int nb = warp_n * 32 + fn * 8;
                bf[fn][0] = *(const uint32_t*)&Bs[nb + g][kk + 2 * tg    ];
                bf[fn][1] = *(const uint32_t*)&Bs[nb + g][kk + 2 * tg + 8];
            }
#pragma unroll
            for (int fm = 0; fm < 4; fm++)
#pragma unroll
                for (int fn = 0; fn < 4; fn++) MMA16816(acc[fm][fn], af[fm], bf[fn]);
        }
    }

    // epilogue: e = exp(score) -> g_e (fp16). Padded c-rows (W rows are 0)
    // produce e=1; harmless, stores in K2 are guarded.
#pragma unroll
    for (int fm = 0; fm < 4; fm++) {
        int c = c0 + warp_m * 64 + fm * 16 + g;
#pragma unroll
        for (int fn = 0; fn < 4; fn++) {
            int sc = s0 + warp_n * 32 + fn * 8 + 2 * tg;
            float e0 = fast_exp(acc[fm][fn][0]);
            float e1 = fast_exp(acc[fm][fn][1]);
            float e2 = fast_exp(acc[fm][fn][2]);
            float e3 = fast_exp(acc[fm][fn][3]);
            *(__half2*)&g_e[(b * CP + c    ) * SS + sc] = __floats2half2_rn(e0, e1);
            *(__half2*)&g_e[(b * CP + c + 8) * SS + sc] = __floats2half2_rn(e2, e3);
        }
    }
}

// ---------------- K1b: deterministic row sums Z[b,c] = sum_s e -------------
__global__ __launch_bounds__(256) void k_rowsum() {
    int gw = (blockIdx.x * 256 + threadIdx.x) >> 5;  // one warp per row
    if (gw >= BB * CP) return;
    int lane = threadIdx.x & 31;
    const __half* p = g_e + gw * SS;
    float sum = 0.0f;
#pragma unroll
    for (int i = 0; i < 16; i++) {
        int4 v = *(const int4*)(p + lane * 8 + i * 256);
        const __half2* h = (const __half2*)&v;
#pragma unroll
        for (int j = 0; j < 4; j++) {
            float2 f = __half22float2(h[j]);
            sum += f.x + f.y;
        }
    }
#pragma unroll
    for (int o = 16; o; o >>= 1) sum += __shfl_xor_sync(0xffffffffu, sum, o);
    if (lane == 0) g_Z[gw] = sum;
}

// ---------------- K2: logits GEMM + normalized attention write --------------
// logits[c,d] = (1/Z[c]) * sum_s e[c,s]*x[s,d];  attn[c,s] = e[c,s]/Z[c]
// CTA tile: 64(c) x 256(d), K=S=4096 in chunks of 32. 8 warps = 2(m) x 4(n),
// warp tile 32x64, frags 2(m) x 8(n).
__global__ __launch_bounds__(256) void k_attnout(float* __restrict__ out_logits,
                                                 float* __restrict__ out_attn) {
    __shared__ __half As[64][KC + 8];
    __shared__ __half Bs[256][KC + 8];

    const int tid = threadIdx.x;
    const int wid = tid >> 5, lane = tid & 31;
    const int g = lane >> 2, tg = lane & 3;
    const int warp_m = wid >> 2, warp_n = wid & 3;

    const int c0 = blockIdx.x * 64;
    const int b  = blockIdx.y;

    float acc[2][8][4];
#pragma unroll
    for (int i = 0; i < 2; i++)
#pragma unroll
        for (int j = 0; j < 8; j++)
#pragma unroll
            for (int k = 0; k < 4; k++) acc[i][j][k] = 0.0f;

    // A (e) loader: 256 slots of int4 (64 rows x 4), 1 per thread; row fixed.
    const int arow = tid >> 2, acol = (tid & 3) * 8;
    const __half* Ab = g_e + (b * CP + c0 + arow) * SS + acol;
    const bool arow_ok = (c0 + arow) < CC;
    const float invZa = 1.0f / __ldg(&g_Z[b * CP + c0 + arow]);
    float* attn_base = out_attn + (b * CC + c0 + arow) * SS + acol;

    // B (xT) loader: 1024 slots (256 rows x 4), 4 per thread; same col.
    const int brow0 = tid >> 2, bcol = (tid & 3) * 8;
    const __half* Bb = g_xT + (b * DD + brow0) * SS + bcol;

    int4 pa, pb[4];
    pa = *(const int4*)(Ab);
#pragma unroll
    for (int i = 0; i < 4; i++) pb[i] = *(const int4*)(Bb + (i * 64) * SS);

#pragma unroll 1
    for (int st = 0; st < SS / KC; st++) {
        __syncthreads();
        *(int4*)&As[arow][acol] = pa;
#pragma unroll
        for (int i = 0; i < 4; i++) *(int4*)&Bs[brow0 + i * 64][bcol] = pb[i];

        // write normalized attention for the A data currently in registers
        if (arow_ok) {
            const __half2* hp = (const __half2*)&pa;
            float* ap = attn_base + st * KC;
            float4 o0, o1;
            float2 f0 = __half22float2(hp[0]);
            float2 f1 = __half22float2(hp[1]);
            float2 f2 = __half22float2(hp[2]);
            float2 f3 = __half22float2(hp[3]);
            o0.x = f0.x * invZa; o0.y = f0.y * invZa;
            o0.z = f1.x * invZa; o0.w = f1.y * invZa;
            o1.x = f2.x * invZa; o1.y = f2.y * invZa;
            o1.z = f3.x * invZa; o1.w = f3.y * invZa;
            *(float4*)(ap)     = o0;
            *(float4*)(ap + 4) = o1;
        }
        __syncthreads();
        if (st + 1 < SS / KC) {
            int sc = (st + 1) * KC;
            pa = *(const int4*)(Ab + sc);
#pragma unroll
            for (int i = 0; i < 4; i++) pb[i] = *(const int4*)(Bb + (i * 64) * SS + sc);
        }
#pragma unroll
        for (int kk = 0; kk < KC; kk += 16) {
            uint32_t af[2][4], bf[8][2];
#pragma unroll
            for (int fm = 0; fm < 2; fm++) {
                int rb = warp_m * 32 + fm * 16;
                af[fm][0] = *(const uint32_t*)&As[rb + g    ][kk + 2 * tg    ];
                af[fm][1] = *(const uint32_t*)&As[rb + g + 8][kk + 2 * tg    ];
                af[fm][2] = *(const uint32_t*)&As[rb + g    ][kk + 2 * tg + 8];
                af[fm][3] = *(const uint32_t*)&As[rb + g + 8][kk + 2 * tg + 8];
            }
#pragma unroll
            for (int fn = 0; fn < 8; fn++) {
                int nb = warp_n * 64 + fn * 8;
                bf[fn][0] = *(const uint32_t*)&Bs[nb + g][kk + 2 * tg    ];
                bf[fn][1] = *(const uint32_t*)&Bs[nb + g][kk + 2 * tg + 8];
            }
#pragma unroll
            for (int fm = 0; fm < 2; fm++)
#pragma unroll
                for (int fn = 0; fn < 8; fn++) MMA16816(acc[fm][fn], af[fm], bf[fn]);
        }
    }

    // epilogue: logits = acc / Z
#pragma unroll
    for (int fm = 0; fm < 2; fm++) {
        int c = c0 + warp_m * 32 + fm * 16 + g;
        float iz0 = 1.0f / __ldg(&g_Z[b * CP + c]);
        float iz1 = 1.0f / __ldg(&g_Z[b * CP + c + 8]);
#pragma unroll
        for (int fn = 0; fn < 8; fn++) {
            int d = warp_n * 64 + fn * 8 + 2 * tg;
            if (c < CC) {
                float2 v; v.x = acc[fm][fn][0] * iz0; v.y = acc[fm][fn][1] * iz0;
                *(float2*)(out_logits + (b * CC + c) * DD + d) = v;
            }
            if (c + 8 < CC) {
                float2 v; v.x = acc[fm][fn][2] * iz1; v.y = acc[fm][fn][3] * iz1;
                *(float2*)(out_logits + (b * CC + c + 8) * DD + d) = v;
            }
        }
    }
}

// ---------------- launch -----------------------------------------------------
extern "C" void kernel_launch(void* const* d_in, const int* in_sizes, int n_in,
                              void* d_out, int out_size) {
    const float* x = (const float*)d_in[0];
    const float* W = (const float*)d_in[1];
    float* logits = (float*)d_out;                       // [B, C, D]
    float* attn   = (float*)d_out + (size_t)BB * CC * DD; // [B, C, S]

    k_convert<<<2048, 256>>>(x, W);
    k_scores<<<dim3(CP / 128, SS / 128, BB), 256>>>();
    k_rowsum<<<(BB * CP) / 8, 256>>>();
    k_attnout<<<dim3(CP / 64, BB), 256>>>(logits, attn);
}

// round 7
// speedup vs baseline: 1.1086x; 1.1086x over previous
#include <cuda_runtime.h>
#include <cuda_fp16.h>
#include <cstdint>

// Problem dims
#define BB 4
#define SS 4096
#define DD 256
#define CC 8921
#define CP 8960   // C padded to multiple of 128
#define KC 32
#define PITCH 40  // halves; 80B rows -> LDSM conflict-free, 16B aligned

// ---------------- device scratch (zero-initialized at module load) ----------
__device__ __align__(256) __half g_xh[BB * SS * DD];            // x fp16 [b][s][d]
__device__ __align__(256) __half g_xT[BB * DD * SS];            // x^T fp16 [b][d][s]
__device__ __align__(256) __half g_Wh[CP * DD];                 // W fp16 (pad rows stay 0)
__device__ __align__(256) __half g_e [(size_t)BB * CP * SS];    // exp(scores) fp16
__device__ __align__(256) float  g_Zp[(size_t)BB * CP * 128];   // per-(row, stile*4+warp) partials
__device__ __align__(256) float  g_Z [BB * CP];                 // row sums

// ---------------- helpers ---------------------------------------------------
__device__ __forceinline__ float fast_exp(float x) {
    float y = x * 1.4426950408889634f;
    y = fminf(fmaxf(y, -80.0f), 80.0f);
    float n = rintf(y);
    float f = y - n;
    float p = 1.3333558146e-3f;
    p = fmaf(p, f, 9.6181291076e-3f);
    p = fmaf(p, f, 5.5504108664e-2f);
    p = fmaf(p, f, 2.4022650696e-1f);
    p = fmaf(p, f, 6.9314718056e-1f);
    p = fmaf(p, f, 1.0f);
    return p * __int_as_float((__float2int_rn(n) + 127) << 23);
}

#define MMA16816(d, a, b)                                                     \
    asm volatile(                                                             \
        "mma.sync.aligned.m16n8k16.row.col.f32.f16.f16.f32 "                  \
        "{%0,%1,%2,%3}, {%4,%5,%6,%7}, {%8,%9}, {%0,%1,%2,%3};\n"             \
        : "+f"((d)[0]), "+f"((d)[1]), "+f"((d)[2]), "+f"((d)[3])              \
        : "r"((a)[0]), "r"((a)[1]), "r"((a)[2]), "r"((a)[3]),                 \
          "r"((b)[0]), "r"((b)[1]))

__device__ __forceinline__ void ldsm4(uint32_t* r, const __half* p) {
    uint32_t a = (uint32_t)__cvta_generic_to_shared(p);
    asm volatile("ldmatrix.sync.aligned.m8n8.x4.shared.b16 {%0,%1,%2,%3}, [%4];\n"
                 : "=r"(r[0]), "=r"(r[1]), "=r"(r[2]), "=r"(r[3]) : "r"(a));
}

// ---------------- K0a: x -> fp16 + transposed fp16 (smem tile transpose) ----
__global__ __launch_bounds__(256) void k_convx(const float* __restrict__ x) {
    __shared__ float t[32][33];
    const int d0 = blockIdx.x * 32, s0 = blockIdx.y * 32, b = blockIdx.z;
    const int tx = threadIdx.x, ty = threadIdx.y;
#pragma unroll
    for (int r = 0; r < 4; r++) {
        int s = s0 + ty + r * 8;
        float v = x[((size_t)b * SS + s) * DD + d0 + tx];
        g_xh[((size_t)b * SS + s) * DD + d0 + tx] = __float2half(v);
        t[ty + r * 8][tx] = v;
    }
    __syncthreads();
#pragma unroll
    for (int r = 0; r < 4; r++) {
        int d = d0 + ty + r * 8;
        g_xT[((size_t)b * DD + d) * SS + s0 + tx] = __float2half(t[tx][ty + r * 8]);
    }
}

// ---------------- K0b: W -> fp16 --------------------------------------------
__global__ __launch_bounds__(256) void k_convw(const float* __restrict__ W) {
    int i0 = blockIdx.x * blockDim.x + threadIdx.x;
    int stride = gridDim.x * blockDim.x;
    for (int i = i0; i < CC * DD; i += stride) g_Wh[i] = __float2half(W[i]);
}

// ---------------- K1: scores GEMM + exp + deterministic partial row sums ----
// CTA 128(c) x 128(s), K=D=256 in chunks of 32, double-buffered, ldmatrix.
__global__ __launch_bounds__(256) void k_scores() {
    __shared__ __half As[2][128][PITCH];
    __shared__ __half Bs[2][128][PITCH];

    const int tid = threadIdx.x;
    const int wid = tid >> 5, lane = tid & 31;
    const int g = lane >> 2, tg = lane & 3;
    const int warp_m = wid >> 2, warp_n = wid & 3;

    const int c0 = blockIdx.x * 128;
    const int s0 = blockIdx.y * 128;
    const int b  = blockIdx.z;

    const __half* Wt = g_Wh + (size_t)c0 * DD;
    const __half* Xt = g_xh + ((size_t)b * SS + s0) * DD;

    float acc[4][4][4];
#pragma unroll
    for (int i = 0; i < 4; i++)
#pragma unroll
        for (int j = 0; j < 4; j++)
#pragma unroll
            for (int k = 0; k < 4; k++) acc[i][j][k] = 0.0f;

    // loaders: 512 int4 slots per tile, 2 per thread (rows r and r+64)
    const int rA0 = tid >> 2, cA0 = (tid & 3) * 8;
    const int rA1 = rA0 + 64;

    // ldmatrix lane address components
    const int a_r = lane & 15, a_c = (lane >> 4) << 3;               // A x4
    const int b_r = ((lane >> 4) << 3) + (lane & 7);                 // B x4 (2 n-tiles)
    const int b_c = ((lane >> 3) & 1) << 3;

    int4 pa0 = *(const int4*)(Wt + rA0 * DD + cA0);
    int4 pa1 = *(const int4*)(Wt + rA1 * DD + cA0);
    int4 pb0 = *(const int4*)(Xt + rA0 * DD + cA0);
    int4 pb1 = *(const int4*)(Xt + rA1 * DD + cA0);
    *(int4*)&As[0][rA0][cA0] = pa0;
    *(int4*)&As[0][rA1][cA0] = pa1;
    *(int4*)&Bs[0][rA0][cA0] = pb0;
    *(int4*)&Bs[0][rA1][cA0] = pb1;
    __syncthreads();

#pragma unroll 1
    for (int st = 0; st < DD / KC; st++) {
        const int buf = st & 1;
        if (st + 1 < DD / KC) {
            int kc = (st + 1) * KC;
            pa0 = *(const int4*)(Wt + rA0 * DD + kc + cA0);
            pa1 = *(const int4*)(Wt + rA1 * DD + kc + cA0);
            pb0 = *(const int4*)(Xt + rA0 * DD + kc + cA0);
            pb1 = *(const int4*)(Xt + rA1 * DD + kc + cA0);
        }
#pragma unroll
        for (int kk = 0; kk < KC; kk += 16) {
            uint32_t af[4][4], bf[4][2];
#pragma unroll
            for (int fm = 0; fm < 4; fm++)
                ldsm4(af[fm], &As[buf][warp_m * 64 + fm * 16 + a_r][kk + a_c]);
#pragma unroll
            for (int fp = 0; fp < 2; fp++) {
                uint32_t t4[4];
                ldsm4(t4, &Bs[buf][warp_n * 32 + fp * 16 + b_r][kk + b_c]);
                bf[2 * fp][0] = t4[0]; bf[2 * fp][1] = t4[1];
                bf[2 * fp + 1][0] = t4[2]; bf[2 * fp + 1][1] = t4[3];
            }
#pragma unroll
            for (int fm = 0; fm < 4; fm++)
#pragma unroll
                for (int fn = 0; fn < 4; fn++) MMA16816(acc[fm][fn], af[fm], bf[fn]);
        }
        if (st + 1 < DD / KC) {
            const int nb = (st + 1) & 1;
            *(int4*)&As[nb][rA0][cA0] = pa0;
            *(int4*)&As[nb][rA1][cA0] = pa1;
            *(int4*)&Bs[nb][rA0][cA0] = pb0;
            *(int4*)&Bs[nb][rA1][cA0] = pb1;
        }
        __syncthreads();
    }

    // epilogue: e = exp(score) -> g_e (streamed), plus deterministic partials
    const int stile4 = blockIdx.y * 4 + warp_n;
#pragma unroll
    for (int fm = 0; fm < 4; fm++) {
        int c = c0 + warp_m * 64 + fm * 16 + g;
        float r0 = 0.0f, r1 = 0.0f;
#pragma unroll
        for (int fn = 0; fn < 4; fn++) {
            int sc = s0 + warp_n * 32 + fn * 8 + 2 * tg;
            float e0 = fast_exp(acc[fm][fn][0]);
            float e1 = fast_exp(acc[fm][fn][1]);
            float e2 = fast_exp(acc[fm][fn][2]);
            float e3 = fast_exp(acc[fm][fn][3]);
            __stcs((__half2*)&g_e[((size_t)b * CP + c    ) * SS + sc], __floats2half2_rn(e0, e1));
            __stcs((__half2*)&g_e[((size_t)b * CP + c + 8) * SS + sc], __floats2half2_rn(e2, e3));
            r0 += e0 + e1;
            r1 += e2 + e3;
        }
        // reduce over the 4 tg lanes (same g) — fixed shuffle order, deterministic
        r0 += __shfl_xor_sync(0xffffffffu, r0, 1);
        r0 += __shfl_xor_sync(0xffffffffu, r0, 2);
        r1 += __shfl_xor_sync(0xffffffffu, r1, 1);
        r1 += __shfl_xor_sync(0xffffffffu, r1, 2);
        if (tg == 0) {
            g_Zp[(size_t)(b * CP + c    ) * 128 + stile4] = r0;
            g_Zp[(size_t)(b * CP + c + 8) * 128 + stile4] = r1;
        }
    }
}

// ---------------- K1b: deterministic final row sums --------------------------
__global__ __launch_bounds__(256) void k_rowsum() {
    int gw = (blockIdx.x * 256 + threadIdx.x) >> 5;  // one warp per row
    if (gw >= BB * CP) return;
    int lane = threadIdx.x & 31;
    float4 v = *(const float4*)(g_Zp + (size_t)gw * 128 + lane * 4);
    float s = v.x + v.y + v.z + v.w;
#pragma unroll
    for (int o = 16; o; o >>= 1) s += __shfl_xor_sync(0xffffffffu, s, o);
    if (lane == 0) g_Z[gw] = s;
}

// ---------------- K2: logits GEMM + normalized attention write ---------------
// CTA 64(c) x 256(d), K=S=4096 in chunks of 32, double-buffered, ldmatrix.
__global__ __launch_bounds__(256) void k_attnout(float* __restrict__ out_logits,
                                                 float* __restrict__ out_attn) {
    extern __shared__ __half sm[];
    __half* Asb = sm;                       // [2][64][PITCH]
    __half* Bsb = sm + 2 * 64 * PITCH;      // [2][256][PITCH]
#define AS2(bf_, r_, c_) Asb[((bf_) * 64 + (r_)) * PITCH + (c_)]
#define BS2(bf_, r_, c_) Bsb[((bf_) * 256 + (r_)) * PITCH + (c_)]

    const int tid = threadIdx.x;
    const int wid = tid >> 5, lane = tid & 31;
    const int g = lane >> 2, tg = lane & 3;
    const int warp_m = wid >> 2, warp_n = wid & 3;

    const int c0 = blockIdx.x * 64;
    const int b  = blockIdx.y;

    float acc[2][8][4];
#pragma unroll
    for (int i = 0; i < 2; i++)
#pragma unroll
        for (int j = 0; j < 8; j++)
#pragma unroll
            for (int k = 0; k < 4; k++) acc[i][j][k] = 0.0f;

    // A loader: 1 int4/thread (64 rows x 4 cols)
    const int arow = tid >> 2, acol = (tid & 3) * 8;
    const __half* Ab = g_e + ((size_t)(b * CP + c0 + arow)) * SS + acol;
    const bool arow_ok = (c0 + arow) < CC;
    const float invZa = 1.0f / g_Z[b * CP + c0 + arow];
    float* attn_base = out_attn + ((size_t)(b * CC + c0 + arow)) * SS + acol;

    // B loader: 4 int4/thread (256 rows x 4 cols, rows +64 apart)
    const int brow = tid >> 2, bcol = (tid & 3) * 8;
    const __half* Bb = g_xT + ((size_t)b * DD + brow) * SS + bcol;

    const int a_r = lane & 15, a_c = (lane >> 4) << 3;
    const int b_r = ((lane >> 4) << 3) + (lane & 7);
    const int b_c = ((lane >> 3) & 1) << 3;

    int4 pa, pb[4];
    pa = __ldcs((const int4*)Ab);
#pragma unroll
    for (int i = 0; i < 4; i++) pb[i] = *(const int4*)(Bb + (size_t)(i * 64) * SS);

    // attention write for chunk 0
    if (arow_ok) {
        const __half2* hp = (const __half2*)&pa;
        float2 f0 = __half22float2(hp[0]), f1 = __half22float2(hp[1]);
        float2 f2 = __half22float2(hp[2]), f3 = __half22float2(hp[3]);
        float4 o0 = {f0.x * invZa, f0.y * invZa, f1.x * invZa, f1.y * invZa};
        float4 o1 = {f2.x * invZa, f2.y * invZa, f3.x * invZa, f3.y * invZa};
        __stwt((float4*)attn_base, o0);
        __stwt((float4*)(attn_base + 4), o1);
    }

    *(int4*)&AS2(0, arow, acol) = pa;
#pragma unroll
    for (int i = 0; i < 4; i++) *(int4*)&BS2(0, brow + i * 64, bcol) = pb[i];
    __syncthreads();

#pragma unroll 1
    for (int st = 0; st < SS / KC; st++) {
        const int buf = st & 1;
        if (st + 1 < SS / KC) {
            int kc = (st + 1) * KC;
            pa = __ldcs((const int4*)(Ab + kc));
#pragma unroll
            for (int i = 0; i < 4; i++) pb[i] = *(const int4*)(Bb + (size_t)(i * 64) * SS + kc);
            if (arow_ok) {
                const __half2* hp = (const __half2*)&pa;
                float2 f0 = __half22float2(hp[0]), f1 = __half22float2(hp[1]);
                float2 f2 = __half22float2(hp[2]), f3 = __half22float2(hp[3]);
                float4 o0 = {f0.x * invZa, f0.y * invZa, f1.x * invZa, f1.y * invZa};
                float4 o1 = {f2.x * invZa, f2.y * invZa, f3.x * invZa, f3.y * invZa};
                float* ap = attn_base + kc;
                __stwt((float4*)ap, o0);
                __stwt((float4*)(ap + 4), o1);
            }
        }
#pragma unroll
        for (int kk = 0; kk < KC; kk += 16) {
            uint32_t af[2][4], bf[8][2];
#pragma unroll
            for (int fm = 0; fm < 2; fm++)
                ldsm4(af[fm], &AS2(buf, warp_m * 32 + fm * 16 + a_r, kk + a_c));
#pragma unroll
            for (int fp = 0; fp < 4; fp++) {
                uint32_t t4[4];
                ldsm4(t4, &BS2(buf, warp_n * 64 + fp * 16 + b_r, kk + b_c));
                bf[2 * fp][0] = t4[0]; bf[2 * fp][1] = t4[1];
                bf[2 * fp + 1][0] = t4[2]; bf[2 * fp + 1][1] = t4[3];
            }
#pragma unroll
            for (int fm = 0; fm < 2; fm++)
#pragma unroll
                for (int fn = 0; fn < 8; fn++) MMA16816(acc[fm][fn], af[fm], bf[fn]);
        }
        if (st + 1 < SS / KC) {
            const int nb = (st + 1) & 1;
            *(int4*)&AS2(nb, arow, acol) = pa;
#pragma unroll
            for (int i = 0; i < 4; i++) *(int4*)&BS2(nb, brow + i * 64, bcol) = pb[i];
        }
        __syncthreads();
    }

    // epilogue: logits = acc / Z (streamed)
#pragma unroll
    for (int fm = 0; fm < 2; fm++) {
        int c = c0 + warp_m * 32 + fm * 16 + g;
        float iz0 = 1.0f / __ldg(&g_Z[b * CP + c]);
        float iz1 = 1.0f / __ldg(&g_Z[b * CP + c + 8]);
#pragma unroll
        for (int fn = 0; fn < 8; fn++) {
            int d = warp_n * 64 + fn * 8 + 2 * tg;
            if (c < CC) {
                float2 v; v.x = acc[fm][fn][0] * iz0; v.y = acc[fm][fn][1] * iz0;
                __stwt((float2*)(out_logits + ((size_t)(b * CC + c)) * DD + d), v);
            }
            if (c + 8 < CC) {
                float2 v; v.x = acc[fm][fn][2] * iz1; v.y = acc[fm][fn][3] * iz1;
                __stwt((float2*)(out_logits + ((size_t)(b * CC + c + 8)) * DD + d), v);
            }
        }
    }
#undef AS2
#undef BS2
}

// ---------------- launch -----------------------------------------------------
extern "C" void kernel_launch(void* const* d_in, const int* in_sizes, int n_in,
                              void* d_out, int out_size) {
    const float* x = (const float*)d_in[0];
    const float* W = (const float*)d_in[1];
    float* logits = (float*)d_out;                        // [B, C, D]
    float* attn   = (float*)d_out + (size_t)BB * CC * DD; // [B, C, S]

    const int k2_smem = 2 * (64 + 256) * PITCH * (int)sizeof(__half);  // 51200
    cudaFuncSetAttribute(k_attnout, cudaFuncAttributeMaxDynamicSharedMemorySize, k2_smem);

    k_convx<<<dim3(DD / 32, SS / 32, BB), dim3(32, 8)>>>(x);
    k_convw<<<256, 256>>>(W);
    k_scores<<<dim3(CP / 128, SS / 128, BB), 256>>>();
    k_rowsum<<<(BB * CP + 7) / 8, 256>>>();
    k_attnout<<<dim3(CP / 64, BB), 256, k2_smem>>>(logits, attn);
}

// round 8
// speedup vs baseline: 1.2844x; 1.1586x over previous
#include <cuda_runtime.h>
#include <cuda_fp16.h>
#include <cstdint>

// Problem dims
#define BB 4
#define SS 4096
#define DD 256
#define CC 8921
#define CP 8960   // C padded to multiple of 128
#define KC 32
#define PITCH 40  // halves; 80B rows -> LDSM conflict-free, 16B aligned

// ---------------- device scratch (zero-initialized at module load) ----------
__device__ __align__(256) __half g_xh[BB * SS * DD];            // x fp16 [b][s][d]
__device__ __align__(256) __half g_xT[BB * DD * SS];            // x^T fp16 [b][d][s]
__device__ __align__(256) __half g_Wh[CP * DD];                 // W fp16 (pad rows stay 0)
__device__ __align__(256) __half g_e [(size_t)BB * CP * SS];    // exp(scores) fp16
__device__ __align__(256) float  g_Zp[(size_t)BB * CP * 128];   // per-(row, stile*4+warp) partials
__device__ __align__(256) float  g_Z [BB * CP];                 // row sums

// ---------------- helpers ---------------------------------------------------
__device__ __forceinline__ float fast_exp(float x) {
    float y = x * 1.4426950408889634f;
    y = fminf(fmaxf(y, -80.0f), 80.0f);
    float n = rintf(y);
    float f = y - n;
    float p = 1.3333558146e-3f;
    p = fmaf(p, f, 9.6181291076e-3f);
    p = fmaf(p, f, 5.5504108664e-2f);
    p = fmaf(p, f, 2.4022650696e-1f);
    p = fmaf(p, f, 6.9314718056e-1f);
    p = fmaf(p, f, 1.0f);
    return p * __int_as_float((__float2int_rn(n) + 127) << 23);
}

#define MMA16816(d, a, b)                                                     \
    asm volatile(                                                             \
        "mma.sync.aligned.m16n8k16.row.col.f32.f16.f16.f32 "                  \
        "{%0,%1,%2,%3}, {%4,%5,%6,%7}, {%8,%9}, {%0,%1,%2,%3};\n"             \
        : "+f"((d)[0]), "+f"((d)[1]), "+f"((d)[2]), "+f"((d)[3])              \
        : "r"((a)[0]), "r"((a)[1]), "r"((a)[2]), "r"((a)[3]),                 \
          "r"((b)[0]), "r"((b)[1]))

__device__ __forceinline__ void ldsm4(uint32_t* r, const __half* p) {
    uint32_t a = (uint32_t)__cvta_generic_to_shared(p);
    asm volatile("ldmatrix.sync.aligned.m8n8.x4.shared.b16 {%0,%1,%2,%3}, [%4];\n"
                 : "=r"(r[0]), "=r"(r[1]), "=r"(r[2]), "=r"(r[3]) : "r"(a));
}

__device__ __forceinline__ void cpa16(const __half* smem_dst, const __half* gmem_src) {
    uint32_t d = (uint32_t)__cvta_generic_to_shared(smem_dst);
    asm volatile("cp.async.cg.shared.global [%0], [%1], 16;\n" :: "r"(d), "l"(gmem_src));
}
#define CP_COMMIT() asm volatile("cp.async.commit_group;\n")
#define CP_WAIT2()  asm volatile("cp.async.wait_group 2;\n")

// ---------------- K0a: x -> fp16 + transposed fp16 --------------------------
// tile 32(s) x 128(d), float4 loads, half2 stores both ways.
__global__ __launch_bounds__(256) void k_convx(const float* __restrict__ x) {
    __shared__ float t[32][132];
    const int d0 = blockIdx.x * 128, s0 = blockIdx.y * 32, b = blockIdx.z;
    const int tid = threadIdx.x;
#pragma unroll
    for (int r = 0; r < 4; r++) {
        int slot = r * 256 + tid;      // 0..1023
        int s = slot >> 5;             // 0..31
        int d = (slot & 31) * 4;
        float4 v = *(const float4*)(x + ((size_t)b * SS + s0 + s) * DD + d0 + d);
        __half2 h0 = __floats2half2_rn(v.x, v.y);
        __half2 h1 = __floats2half2_rn(v.z, v.w);
        *(__half2*)(g_xh + ((size_t)b * SS + s0 + s) * DD + d0 + d)     = h0;
        *(__half2*)(g_xh + ((size_t)b * SS + s0 + s) * DD + d0 + d + 2) = h1;
        *(float4*)&t[s][d] = v;
    }
    __syncthreads();
#pragma unroll
    for (int r = 0; r < 8; r++) {
        int slot = r * 256 + tid;      // 0..2047
        int d = slot >> 4;             // 0..127
        int sp = slot & 15;            // s-pair
        __half2 h = __floats2half2_rn(t[2 * sp][d], t[2 * sp + 1][d]);
        *(__half2*)(g_xT + ((size_t)b * DD + d0 + d) * SS + s0 + 2 * sp) = h;
    }
}

// ---------------- K0b: W -> fp16 --------------------------------------------
__global__ __launch_bounds__(256) void k_convw(const float* __restrict__ W) {
    int i0 = blockIdx.x * blockDim.x + threadIdx.x;
    int stride = gridDim.x * blockDim.x;
    for (int i = i0; i < CC * DD; i += stride) g_Wh[i] = __float2half(W[i]);
}

// ---------------- K1: scores GEMM + exp + deterministic partial row sums ----
// CTA 128(c) x 128(s), K=D=256 in 8 chunks of 32, 4-stage cp.async ring.
__global__ __launch_bounds__(256) void k_scores() {
    extern __shared__ __half sm1[];
    __half* Asb = sm1;                          // [4][128][PITCH]
    __half* Bsb = sm1 + 4 * 128 * PITCH;        // [4][128][PITCH]
#define A1(st_, r_, c_) Asb[(((st_) * 128) + (r_)) * PITCH + (c_)]
#define B1(st_, r_, c_) Bsb[(((st_) * 128) + (r_)) * PITCH + (c_)]

    const int tid = threadIdx.x;
    const int wid = tid >> 5, lane = tid & 31;
    const int g = lane >> 2, tg = lane & 3;
    const int warp_m = wid >> 2, warp_n = wid & 3;

    const int c0 = blockIdx.x * 128;
    const int s0 = blockIdx.y * 128;
    const int b  = blockIdx.z;

    const __half* Wt = g_Wh + (size_t)c0 * DD;
    const __half* Xt = g_xh + ((size_t)b * SS + s0) * DD;

    float acc[4][4][4];
#pragma unroll
    for (int i = 0; i < 4; i++)
#pragma unroll
        for (int j = 0; j < 4; j++)
#pragma unroll
            for (int k = 0; k < 4; k++) acc[i][j][k] = 0.0f;

    const int rA = tid >> 2, cA = (tid & 3) * 8;  // rows rA, rA+64

    // ldmatrix lane address components
    const int a_r = lane & 15, a_c = (lane >> 4) << 3;
    const int b_r = ((lane >> 4) << 3) + (lane & 7);
    const int b_c = ((lane >> 3) & 1) << 3;

    // prologue: stages 0..2
#pragma unroll
    for (int st = 0; st < 3; st++) {
        int kc = st * KC;
        cpa16(&A1(st, rA,      cA), Wt + (size_t)rA * DD + kc + cA);
        cpa16(&A1(st, rA + 64, cA), Wt + (size_t)(rA + 64) * DD + kc + cA);
        cpa16(&B1(st, rA,      cA), Xt + (size_t)rA * DD + kc + cA);
        cpa16(&B1(st, rA + 64, cA), Xt + (size_t)(rA + 64) * DD + kc + cA);
        CP_COMMIT();
    }

#pragma unroll 1
    for (int st = 0; st < DD / KC; st++) {
        const int buf = st & 3;
        CP_WAIT2();
        __syncthreads();
        if (st + 3 < DD / KC) {
            const int ns = (st + 3) & 3;
            const int kc = (st + 3) * KC;
            cpa16(&A1(ns, rA,      cA), Wt + (size_t)rA * DD + kc + cA);
            cpa16(&A1(ns, rA + 64, cA), Wt + (size_t)(rA + 64) * DD + kc + cA);
            cpa16(&B1(ns, rA,      cA), Xt + (size_t)rA * DD + kc + cA);
            cpa16(&B1(ns, rA + 64, cA), Xt + (size_t)(rA + 64) * DD + kc + cA);
        }
        CP_COMMIT();
#pragma unroll
        for (int kk = 0; kk < KC; kk += 16) {
            uint32_t af[4][4], bf[4][2];
#pragma unroll
            for (int fm = 0; fm < 4; fm++)
                ldsm4(af[fm], &A1(buf, warp_m * 64 + fm * 16 + a_r, kk + a_c));
#pragma unroll
            for (int fp = 0; fp < 2; fp++) {
                uint32_t t4[4];
                ldsm4(t4, &B1(buf, warp_n * 32 + fp * 16 + b_r, kk + b_c));
                bf[2 * fp][0] = t4[0]; bf[2 * fp][1] = t4[1];
                bf[2 * fp + 1][0] = t4[2]; bf[2 * fp + 1][1] = t4[3];
            }
#pragma unroll
            for (int fm = 0; fm < 4; fm++)
#pragma unroll
                for (int fn = 0; fn < 4; fn++) MMA16816(acc[fm][fn], af[fm], bf[fn]);
        }
    }

    // epilogue: e = exp(score) -> g_e (streamed), plus deterministic partials
    const int stile4 = blockIdx.y * 4 + warp_n;
#pragma unroll
    for (int fm = 0; fm < 4; fm++) {
        int c = c0 + warp_m * 64 + fm * 16 + g;
        float r0 = 0.0f, r1 = 0.0f;
#pragma unroll
        for (int fn = 0; fn < 4; fn++) {
            int sc = s0 + warp_n * 32 + fn * 8 + 2 * tg;
            float e0 = fast_exp(acc[fm][fn][0]);
            float e1 = fast_exp(acc[fm][fn][1]);
            float e2 = fast_exp(acc[fm][fn][2]);
            float e3 = fast_exp(acc[fm][fn][3]);
            __stcs((__half2*)&g_e[((size_t)b * CP + c    ) * SS + sc], __floats2half2_rn(e0, e1));
            __stcs((__half2*)&g_e[((size_t)b * CP + c + 8) * SS + sc], __floats2half2_rn(e2, e3));
            r0 += e0 + e1;
            r1 += e2 + e3;
        }
        r0 += __shfl_xor_sync(0xffffffffu, r0, 1);
        r0 += __shfl_xor_sync(0xffffffffu, r0, 2);
        r1 += __shfl_xor_sync(0xffffffffu, r1, 1);
        r1 += __shfl_xor_sync(0xffffffffu, r1, 2);
        if (tg == 0) {
            g_Zp[(size_t)(b * CP + c    ) * 128 + stile4] = r0;
            g_Zp[(size_t)(b * CP + c + 8) * 128 + stile4] = r1;
        }
    }
#undef A1
#undef B1
}

// ---------------- K1b: deterministic final row sums --------------------------
__global__ __launch_bounds__(256) void k_rowsum() {
    int gw = (blockIdx.x * 256 + threadIdx.x) >> 5;
    if (gw >= BB * CP) return;
    int lane = threadIdx.x & 31;
    float4 v = *(const float4*)(g_Zp + (size_t)gw * 128 + lane * 4);
    float s = v.x + v.y + v.z + v.w;
#pragma unroll
    for (int o = 16; o; o >>= 1) s += __shfl_xor_sync(0xffffffffu, s, o);
    if (lane == 0) g_Z[gw] = s;
}

// ---------------- K2: logits GEMM + normalized attention write ---------------
// CTA 64(c) x 256(d), K=S=4096 in 128 chunks of 32, 4-stage cp.async ring.
__global__ __launch_bounds__(256) void k_attnout(float* __restrict__ out_logits,
                                                 float* __restrict__ out_attn) {
    extern __shared__ __half sm2[];
    __half* Asb = sm2;                         // [4][64][PITCH]
    __half* Bsb = sm2 + 4 * 64 * PITCH;        // [4][256][PITCH]
#define A2(st_, r_, c_) Asb[(((st_) * 64)  + (r_)) * PITCH + (c_)]
#define B2(st_, r_, c_) Bsb[(((st_) * 256) + (r_)) * PITCH + (c_)]

    const int tid = threadIdx.x;
    const int wid = tid >> 5, lane = tid & 31;
    const int g = lane >> 2, tg = lane & 3;
    const int warp_m = wid >> 2, warp_n = wid & 3;

    const int c0 = blockIdx.x * 64;
    const int b  = blockIdx.y;

    float acc[2][8][4];
#pragma unroll
    for (int i = 0; i < 2; i++)
#pragma unroll
        for (int j = 0; j < 8; j++)
#pragma unroll
            for (int k = 0; k < 4; k++) acc[i][j][k] = 0.0f;

    const int arow = tid >> 2, acol = (tid & 3) * 8;
    const __half* Ab = g_e + ((size_t)(b * CP + c0 + arow)) * SS + acol;
    const bool arow_ok = (c0 + arow) < CC;
    const float invZa = 1.0f / g_Z[b * CP + c0 + arow];
    float* attn_base = out_attn + ((size_t)(b * CC + c0 + arow)) * SS + acol;

    const int brow = tid >> 2, bcol = (tid & 3) * 8;
    const __half* Bb = g_xT + ((size_t)b * DD + brow) * SS + bcol;

    const int a_r = lane & 15, a_c = (lane >> 4) << 3;
    const int b_r = ((lane >> 4) << 3) + (lane & 7);
    const int b_c = ((lane >> 3) & 1) << 3;

    // prologue: stages 0..2
#pragma unroll
    for (int st = 0; st < 3; st++) {
        int kc = st * KC;
        cpa16(&A2(st, arow, acol), Ab + kc);
#pragma unroll
        for (int i = 0; i < 4; i++)
            cpa16(&B2(st, brow + i * 64, bcol), Bb + (size_t)(i * 64) * SS + kc);
        CP_COMMIT();
    }

#pragma unroll 1
    for (int st = 0; st < SS / KC; st++) {
        const int buf = st & 3;
        CP_WAIT2();
        __syncthreads();
        if (st + 3 < SS / KC) {
            const int ns = (st + 3) & 3;
            const int kc = (st + 3) * KC;
            cpa16(&A2(ns, arow, acol), Ab + kc);
#pragma unroll
            for (int i = 0; i < 4; i++)
                cpa16(&B2(ns, brow + i * 64, bcol), Bb + (size_t)(i * 64) * SS + kc);
        }
        CP_COMMIT();

        // normalized attention write from the just-arrived A stage
        if (arow_ok) {
            int4 e4 = *(const int4*)&A2(buf, arow, acol);
            const __half2* hp = (const __half2*)&e4;
            float2 f0 = __half22float2(hp[0]), f1 = __half22float2(hp[1]);
            float2 f2 = __half22float2(hp[2]), f3 = __half22float2(hp[3]);
            float4 o0 = {f0.x * invZa, f0.y * invZa, f1.x * invZa, f1.y * invZa};
            float4 o1 = {f2.x * invZa, f2.y * invZa, f3.x * invZa, f3.y * invZa};
            float* ap = attn_base + st * KC;
            __stwt((float4*)ap, o0);
            __stwt((float4*)(ap + 4), o1);
        }

#pragma unroll
        for (int kk = 0; kk < KC; kk += 16) {
            uint32_t af[2][4], bf[8][2];
#pragma unroll
            for (int fm = 0; fm < 2; fm++)
                ldsm4(af[fm], &A2(buf, warp_m * 32 + fm * 16 + a_r, kk + a_c));
#pragma unroll
            for (int fp = 0; fp < 4; fp++) {
                uint32_t t4[4];
                ldsm4(t4, &B2(buf, warp_n * 64 + fp * 16 + b_r, kk + b_c));
                bf[2 * fp][0] = t4[0]; bf[2 * fp][1] = t4[1];
                bf[2 * fp + 1][0] = t4[2]; bf[2 * fp + 1][1] = t4[3];
            }
#pragma unroll
            for (int fm = 0; fm < 2; fm++)
#pragma unroll
                for (int fn = 0; fn < 8; fn++) MMA16816(acc[fm][fn], af[fm], bf[fn]);
        }
    }

    // epilogue: logits = acc / Z (streamed)
#pragma unroll
    for (int fm = 0; fm < 2; fm++) {
        int c = c0 + warp_m * 32 + fm * 16 + g;
        float iz0 = 1.0f / __ldg(&g_Z[b * CP + c]);
        float iz1 = 1.0f / __ldg(&g_Z[b * CP + c + 8]);
#pragma unroll
        for (int fn = 0; fn < 8; fn++) {
            int d = warp_n * 64 + fn * 8 + 2 * tg;
            if (c < CC) {
                float2 v; v.x = acc[fm][fn][0] * iz0; v.y = acc[fm][fn][1] * iz0;
                __stwt((float2*)(out_logits + ((size_t)(b * CC + c)) * DD + d), v);
            }
            if (c + 8 < CC) {
                float2 v; v.x = acc[fm][fn][2] * iz1; v.y = acc[fm][fn][3] * iz1;
                __stwt((float2*)(out_logits + ((size_t)(b * CC + c + 8)) * DD + d), v);
            }
        }
    }
#undef A2
#undef B2
}

// ---------------- launch -----------------------------------------------------
extern "C" void kernel_launch(void* const* d_in, const int* in_sizes, int n_in,
                              void* d_out, int out_size) {
    const float* x = (const float*)d_in[0];
    const float* W = (const float*)d_in[1];
    float* logits = (float*)d_out;                        // [B, C, D]
    float* attn   = (float*)d_out + (size_t)BB * CC * DD; // [B, C, S]

    const int k1_smem = 4 * (128 + 128) * PITCH * (int)sizeof(__half);  // 81920
    const int k2_smem = 4 * (64 + 256) * PITCH * (int)sizeof(__half);   // 102400
    cudaFuncSetAttribute(k_scores,  cudaFuncAttributeMaxDynamicSharedMemorySize, k1_smem);
    cudaFuncSetAttribute(k_attnout, cudaFuncAttributeMaxDynamicSharedMemorySize, k2_smem);

    k_convx<<<dim3(DD / 128, SS / 32, BB), 256>>>(x);
    k_convw<<<256, 256>>>(W);
    k_scores<<<dim3(CP / 128, SS / 128, BB), 256, k1_smem>>>();
    k_rowsum<<<(BB * CP + 7) / 8, 256>>>();
    k_attnout<<<dim3(CP / 64, BB), 256, k2_smem>>>(logits, attn);
}